// round 1
// baseline (speedup 1.0000x reference)
#include <cuda_runtime.h>
#include <cstdint>

#define NSTATES 2048
#define NSYM    512
#define TLEN    8192
#define NBLK    128
#define NTHR    512
#define WARPS   (NTHR / 32)

// Scratch: transposed A (At[s][j] = A[j][s]), per-step nonzero flags, barrier state.
__device__ float             g_At[(size_t)NSTATES * NSTATES];
__device__ unsigned          g_flags[TLEN];
__device__ volatile unsigned g_bar_gen;   // monotone across graph replays (safe)
__device__ unsigned          g_bar_cnt;   // returns to 0 after every barrier

__device__ __forceinline__ void grid_barrier() {
    __threadfence();
    __syncthreads();
    if (threadIdx.x == 0) {
        unsigned g = g_bar_gen;
        unsigned a = atomicAdd(&g_bar_cnt, 1u);
        if (a == NBLK - 1) {
            g_bar_cnt = 0;
            __threadfence();
            g_bar_gen = g + 1;
        } else {
            while (g_bar_gen == g) { }
        }
    }
    __syncthreads();
}

__global__ __launch_bounds__(NTHR, 1)
void hmm_forward_kernel(const int* __restrict__ obs,
                        const float* __restrict__ A,
                        const float* __restrict__ B,
                        const float* __restrict__ pi,
                        float* __restrict__ out)
{
    __shared__ float s_alpha[NSTATES];
    __shared__ float s_tile[32][33];
    __shared__ int   s_nz;

    const int tid  = threadIdx.x;
    const int lane = tid & 31;
    const int wid  = tid >> 5;

    // ---------------- Phase 0: transpose A -> g_At (32x32 smem tiles) ----------------
    {
        const int x  = tid & 31;       // 0..31
        const int y0 = tid >> 5;       // 0..15
        const int NT = NSTATES / 32;   // 64 tiles per dim
        for (int tile = blockIdx.x; tile < NT * NT; tile += NBLK) {
            const int tr = tile / NT;  // source row block (j)
            const int tc = tile % NT;  // source col block (s)
            #pragma unroll
            for (int yy = 0; yy < 32; yy += 16)
                s_tile[y0 + yy][x] = A[(size_t)(tr * 32 + y0 + yy) * NSTATES + tc * 32 + x];
            __syncthreads();
            #pragma unroll
            for (int yy = 0; yy < 32; yy += 16)
                g_At[(size_t)(tc * 32 + y0 + yy) * NSTATES + tr * 32 + x] = s_tile[x][y0 + yy];
            __syncthreads();
        }
    }

    // Reset flags (must happen every graph replay) + alpha0
    {
        const int gid = blockIdx.x * NTHR + tid;
        for (int i = gid; i < TLEN; i += NBLK * NTHR) g_flags[i] = 0u;
        const int o0 = obs[0];
        for (int s = gid; s < NSTATES; s += NBLK * NTHR)
            out[s] = pi[s] * B[(size_t)s * NSYM + o0];
    }

    grid_barrier();

    // ---------------- Main loop: warp-per-state GEMV ----------------
    const int s = blockIdx.x * WARPS + wid;              // this warp's state (0..2047)
    const float4* Atv = (const float4*)(g_At + (size_t)s * NSTATES);

    int t;
    for (t = 1; t < TLEN; ++t) {
        // Stage alpha_{t-1} into smem (L1-bypass to guarantee freshness across SMs)
        const float4* prev4 = (const float4*)(out + (size_t)(t - 1) * NSTATES);
        float4* s4 = (float4*)s_alpha;
        if (tid == 0) s_nz = 0;
        s4[tid] = __ldcg(prev4 + tid);                   // 512 float4 / 512 threads
        __syncthreads();

        float sum0 = 0.f, sum1 = 0.f;
        #pragma unroll
        for (int k = 0; k < 16; k += 2) {
            float4 a0 = Atv[lane + (k << 5)];
            float4 p0 = s4[lane + (k << 5)];
            float4 a1 = Atv[lane + ((k + 1) << 5)];
            float4 p1 = s4[lane + ((k + 1) << 5)];
            sum0 += a0.x * p0.x + a0.y * p0.y + a0.z * p0.z + a0.w * p0.w;
            sum1 += a1.x * p1.x + a1.y * p1.y + a1.z * p1.z + a1.w * p1.w;
        }
        float sum = sum0 + sum1;
        #pragma unroll
        for (int off = 16; off; off >>= 1)
            sum += __shfl_xor_sync(0xFFFFFFFFu, sum, off);

        if (lane == 0) {
            const int o = obs[t];
            const float v = sum * B[(size_t)s * NSYM + o];
            out[(size_t)t * NSTATES + s] = v;
            if (v != 0.f) s_nz = 1;                      // benign race, all write 1
        }
        __syncthreads();
        if (tid == 0 && s_nz) atomicOr(&g_flags[t], 1u);

        grid_barrier();

        const unsigned nz = *((volatile unsigned*)&g_flags[t]);
        if (!nz) { ++t; break; }                         // row t is exactly all-zero -> rest is zero
    }

    // ---------------- Tail: zero-fill rows t..TLEN-1 (exact continuation) ----------------
    if (t < TLEN) {
        float4* out4 = (float4*)out;
        const size_t begin  = (size_t)t * (NSTATES / 4);
        const size_t total4 = (size_t)TLEN * (NSTATES / 4);
        const float4 z = make_float4(0.f, 0.f, 0.f, 0.f);
        for (size_t i = begin + (size_t)blockIdx.x * NTHR + tid; i < total4;
             i += (size_t)NBLK * NTHR)
            out4[i] = z;
    }
}

extern "C" void kernel_launch(void* const* d_in, const int* in_sizes, int n_in,
                              void* d_out, int out_size)
{
    (void)in_sizes; (void)n_in; (void)out_size;
    const int*   obs = (const int*)d_in[0];
    const float* A   = (const float*)d_in[1];
    const float* B   = (const float*)d_in[2];
    const float* pi  = (const float*)d_in[3];
    float*       out = (float*)d_out;
    hmm_forward_kernel<<<NBLK, NTHR>>>(obs, A, B, pi, out);
}

// round 4
// speedup vs baseline: 1.6212x; 1.6212x over previous
#include <cuda_runtime.h>
#include <cstdint>

#define NSTATES 2048
#define NSYM    512
#define TLEN    8192
#define NBLK    128
#define NTHR    512
#define WARPS   (NTHR / 32)
#define SPS     (NSTATES / NBLK)   // states per CTA = 16 (one per warp)

// Scratch: transposed A (At[s][j] = A[j][s]) staged through L2; barrier state.
__device__ float             g_At[(size_t)NSTATES * NSTATES];
__device__ volatile unsigned g_bar_gen;   // monotone across graph replays (safe: read-then-wait-for-change)
__device__ unsigned          g_bar_cnt;   // low 16: arrivals, high 16: nz votes; returns to 0 each barrier
__device__ volatile unsigned g_nz_res;    // written by last arriver before gen release

// Grid barrier with nonzero-vote aggregation. Called by tid==0 of each CTA.
// Returns total number of CTAs that voted nonzero.
__device__ __forceinline__ unsigned grid_bar_nz(unsigned cta_nz) {
    const unsigned g = g_bar_gen;
    const unsigned old = atomicAdd(&g_bar_cnt, 1u | (cta_nz << 16));
    if ((old & 0xFFFFu) == NBLK - 1) {
        const unsigned tot = (old >> 16) + cta_nz;
        g_nz_res = tot;
        *((volatile unsigned*)&g_bar_cnt) = 0u;
        __threadfence();
        g_bar_gen = g + 1;
        return tot;
    }
    while (g_bar_gen == g) { }
    return g_nz_res;
}

__global__ __launch_bounds__(NTHR, 1)
void hmm_forward_kernel(const int* __restrict__ obs,
                        const float* __restrict__ A,
                        const float* __restrict__ B,
                        const float* __restrict__ pi,
                        float* __restrict__ out)
{
    extern __shared__ float sm[];
    float* s_At = sm;                       // SPS * NSTATES floats = 128 KB
    float* s_al = sm + SPS * NSTATES;       // NSTATES floats = 8 KB
    __shared__ unsigned s_nz;

    const int tid  = threadIdx.x;
    const int lane = tid & 31;
    const int wid  = tid >> 5;

    // ---------------- Phase 0a: transpose A -> g_At (32x32 smem tiles) ----------------
    // Tile buffer aliases the s_At region (At is loaded only after the grid barrier).
    {
        float (*s_tile)[33] = (float (*)[33])sm;
        const int x  = tid & 31;
        const int y0 = tid >> 5;       // 0..15
        const int NT = NSTATES / 32;   // 64
        for (int tile = blockIdx.x; tile < NT * NT; tile += NBLK) {
            const int tr = tile / NT;
            const int tc = tile % NT;
            #pragma unroll
            for (int yy = 0; yy < 32; yy += 16)
                s_tile[y0 + yy][x] = A[(size_t)(tr * 32 + y0 + yy) * NSTATES + tc * 32 + x];
            __syncthreads();
            #pragma unroll
            for (int yy = 0; yy < 32; yy += 16)
                g_At[(size_t)(tc * 32 + y0 + yy) * NSTATES + tr * 32 + x] = s_tile[x][y0 + yy];
            __syncthreads();
        }
    }

    // ---------------- Phase 0b: alpha0 ----------------
    {
        const int gid = blockIdx.x * NTHR + tid;
        const int o0 = __ldcg(obs);
        for (int s = gid; s < NSTATES; s += NBLK * NTHR)
            out[s] = pi[s] * B[(size_t)s * NSYM + o0];
    }

    __threadfence();
    __syncthreads();
    if (tid == 0) (void)grid_bar_nz(1u);
    __syncthreads();

    // ---------------- Load this CTA's At slice into smem (L2 -> smem, 128 KB) ----------------
    {
        const float4* gAt4 = (const float4*)(g_At + (size_t)(blockIdx.x * SPS) * NSTATES);
        float4* sAt4 = (float4*)s_At;
        #pragma unroll 4
        for (int i = tid; i < SPS * NSTATES / 4; i += NTHR)
            sAt4[i] = __ldcg(gAt4 + i);
        __syncthreads();
    }

    // ---------------- Main loop: warp-per-state GEMV from smem ----------------
    const int s = blockIdx.x * SPS + wid;
    const float4* Arow = (const float4*)(s_At + wid * NSTATES);
    const float4* al4  = (const float4*)s_al;

    // Prefetch emission for t=1 (only lane 0 consumes it)
    float em = 0.f;
    if (lane == 0) {
        const int o1 = __ldcg(obs + 1);
        em = __ldcg(&B[(size_t)s * NSYM + o1]);
    }

    int t;
    for (t = 1; t < TLEN; ++t) {
        // Stage alpha_{t-1} into smem (L2-coherent read)
        ((float4*)s_al)[tid] = __ldcg(((const float4*)(out + (size_t)(t - 1) * NSTATES)) + tid);
        if (tid == 0) s_nz = 0u;
        // Prefetch next observation early
        int o_next = 0;
        if (lane == 0 && t + 1 < TLEN) o_next = __ldcg(obs + t + 1);
        __syncthreads();

        float sum0 = 0.f, sum1 = 0.f;
        #pragma unroll
        for (int k = 0; k < 16; k += 2) {
            float4 a0 = Arow[(k << 5) + lane];
            float4 p0 = al4[(k << 5) + lane];
            float4 a1 = Arow[((k + 1) << 5) + lane];
            float4 p1 = al4[((k + 1) << 5) + lane];
            sum0 += a0.x * p0.x + a0.y * p0.y + a0.z * p0.z + a0.w * p0.w;
            sum1 += a1.x * p1.x + a1.y * p1.y + a1.z * p1.z + a1.w * p1.w;
        }
        float sum = sum0 + sum1;
        #pragma unroll
        for (int off = 16; off; off >>= 1)
            sum += __shfl_xor_sync(0xFFFFFFFFu, sum, off);

        if (lane == 0) {
            const float v = sum * em;
            out[(size_t)t * NSTATES + s] = v;
            if (v != 0.f) s_nz = 1u;                 // benign race, all write 1
            // Prefetch emission for next step (latency hidden by barrier + staging)
            em = __ldcg(&B[(size_t)s * NSYM + o_next]);
        }

        __threadfence();   // order row-t stores before barrier arrival
        __syncthreads();
        if (tid == 0) s_nz = grid_bar_nz(s_nz ? 1u : 0u);
        __syncthreads();

        if (!s_nz) { ++t; break; }   // row t is exactly all-zero -> all later rows are zero
    }

    // ---------------- Tail: zero-fill rows t..TLEN-1 ----------------
    if (t < TLEN) {
        float4* out4 = (float4*)out;
        const size_t begin  = (size_t)t * (NSTATES / 4);
        const size_t total4 = (size_t)TLEN * (NSTATES / 4);
        const float4 z = make_float4(0.f, 0.f, 0.f, 0.f);
        for (size_t i = begin + (size_t)blockIdx.x * NTHR + tid; i < total4;
             i += (size_t)NBLK * NTHR)
            out4[i] = z;
    }
}

extern "C" void kernel_launch(void* const* d_in, const int* in_sizes, int n_in,
                              void* d_out, int out_size)
{
    (void)in_sizes; (void)n_in; (void)out_size;
    const int*   obs = (const int*)d_in[0];
    const float* A   = (const float*)d_in[1];
    const float* B   = (const float*)d_in[2];
    const float* pi  = (const float*)d_in[3];
    float*       out = (float*)d_out;

    const int smem_bytes = (SPS * NSTATES + NSTATES) * (int)sizeof(float);  // 136 KB
    cudaFuncSetAttribute(hmm_forward_kernel,
                         cudaFuncAttributeMaxDynamicSharedMemorySize, smem_bytes);
    hmm_forward_kernel<<<NBLK, NTHR, smem_bytes>>>(obs, A, B, pi, out);
}

// round 7
// speedup vs baseline: 2.0122x; 1.2412x over previous
#include <cuda_runtime.h>
#include <cstdint>

#define NSTATES 2048
#define NSYM    512
#define TLEN    8192
#define NBLK    128
#define NTHR    512
#define SPS     16               // states per CTA
#define QRT     (NSTATES / 4)    // j-values per quarter

// Central barrier state (proven R2/R4 protocol; graph-replay safe: gen is
// monotone, cnt returns to 0 after every barrier).
__device__ volatile unsigned g_bar_gen;
__device__ unsigned          g_bar_cnt;   // low 16: arrivals, high 16: nz votes
__device__ volatile unsigned g_nz_res;

// Called by tid==0 of each CTA. Returns total nonzero votes.
__device__ __forceinline__ unsigned grid_bar_nz(unsigned cta_nz) {
    const unsigned g = g_bar_gen;
    const unsigned old = atomicAdd(&g_bar_cnt, 1u | (cta_nz << 16));
    if ((old & 0xFFFFu) == NBLK - 1) {
        const unsigned tot = (old >> 16) + cta_nz;
        g_nz_res = tot;
        *((volatile unsigned*)&g_bar_cnt) = 0u;
        __threadfence();
        g_bar_gen = g + 1;
        return tot;
    }
    while (g_bar_gen == g) { }
    return g_nz_res;
}

__global__ __launch_bounds__(NTHR, 1)
void hmm_forward_kernel(const int* __restrict__ obs,
                        const float* __restrict__ A,
                        const float* __restrict__ B,
                        const float* __restrict__ pi,
                        float* __restrict__ out)
{
    extern __shared__ float s_At[];          // [SPS][NSTATES] = 128 KB, s_At[c][j] = A[j][sbase+c]
    __shared__ float s_part[4][SPS];         // [quarter][local state]
    __shared__ unsigned s_nz;

    const int tid   = threadIdx.x;
    const int lane  = tid & 31;
    const int wid   = tid >> 5;
    const int b     = blockIdx.x;
    const int sbase = b * SPS;
    const int my_s  = sbase + (lane & 15);   // warp0, lanes<16

    float em = 0.f;                          // B[my_s][obs[t]] for the upcoming row t

    // ---------------- Row 0 + em prefetch (warp 0) ----------------
    unsigned nz0 = 1u;
    if (wid == 0) {
        float v = 0.f;
        if (lane < SPS) {
            const int o0 = __ldcg(obs);
            v = __ldcg(pi + my_s) * __ldcg(B + (size_t)my_s * NSYM + o0);
            __stcg(out + my_s, v);
        }
        __threadfence();
        nz0 = __ballot_sync(0xFFFFFFFFu, v != 0.f) ? 1u : 0u;
        if (lane < SPS) {
            const int o1 = __ldcg(obs + 1);
            em = __ldcg(B + (size_t)my_s * NSYM + o1);
        }
    }

    // ---------------- Load A columns [sbase, sbase+16) from global, transpose into smem ----------------
    {
        const int r  = tid >> 2;             // 0..127
        const int c0 = (tid & 3) << 2;       // 0,4,8,12
        const float* Ag = A + sbase + c0;
        #pragma unroll
        for (int p = 0; p < 16; p += 4) {
            const int j0 = (p + 0) * 128 + r, j1 = (p + 1) * 128 + r;
            const int j2 = (p + 2) * 128 + r, j3 = (p + 3) * 128 + r;
            float4 v0 = __ldcg((const float4*)(Ag + (size_t)j0 * NSTATES));
            float4 v1 = __ldcg((const float4*)(Ag + (size_t)j1 * NSTATES));
            float4 v2 = __ldcg((const float4*)(Ag + (size_t)j2 * NSTATES));
            float4 v3 = __ldcg((const float4*)(Ag + (size_t)j3 * NSTATES));
            s_At[(c0+0)*NSTATES + j0] = v0.x; s_At[(c0+1)*NSTATES + j0] = v0.y;
            s_At[(c0+2)*NSTATES + j0] = v0.z; s_At[(c0+3)*NSTATES + j0] = v0.w;
            s_At[(c0+0)*NSTATES + j1] = v1.x; s_At[(c0+1)*NSTATES + j1] = v1.y;
            s_At[(c0+2)*NSTATES + j1] = v1.z; s_At[(c0+3)*NSTATES + j1] = v1.w;
            s_At[(c0+0)*NSTATES + j2] = v2.x; s_At[(c0+1)*NSTATES + j2] = v2.y;
            s_At[(c0+2)*NSTATES + j2] = v2.z; s_At[(c0+3)*NSTATES + j2] = v2.w;
            s_At[(c0+0)*NSTATES + j3] = v3.x; s_At[(c0+1)*NSTATES + j3] = v3.y;
            s_At[(c0+2)*NSTATES + j3] = v3.z; s_At[(c0+3)*NSTATES + j3] = v3.w;
        }
    }
    __syncthreads();
    if (tid == 0) s_nz = grid_bar_nz(nz0);   // publishes row 0 to all CTAs
    __syncthreads();

    // ---------------- Main loop: register-tile GEMV ----------------
    const int a = wid >> 2;                  // local states 4a..4a+3
    const int q = wid & 3;                   // j quarter
    const float4* row0 = (const float4*)(s_At + (size_t)(4*a + 0) * NSTATES + q * QRT);
    const float4* row1 = (const float4*)(s_At + (size_t)(4*a + 1) * NSTATES + q * QRT);
    const float4* row2 = (const float4*)(s_At + (size_t)(4*a + 2) * NSTATES + q * QRT);
    const float4* row3 = (const float4*)(s_At + (size_t)(4*a + 3) * NSTATES + q * QRT);

    int t;
    for (t = 1; t < TLEN; ++t) {
        if (!s_nz) break;                    // row t-1 exactly all-zero -> rows t.. all zero

        // alpha quarter straight into registers (L2-coherent)
        const float4* al = (const float4*)(out + (size_t)(t - 1) * NSTATES) + q * (QRT / 4);
        float4 p0 = __ldcg(al + lane);
        float4 p1 = __ldcg(al + lane + 32);
        float4 p2 = __ldcg(al + lane + 64);
        float4 p3 = __ldcg(al + lane + 96);

        int o_next = 0;
        if (wid == 0 && lane < SPS)
            o_next = __ldcg(obs + ((t + 1 < TLEN) ? t + 1 : t));

        float acc0, acc1, acc2, acc3;
        {
            float4 x;
            x = row0[lane];      acc0  = x.x*p0.x + x.y*p0.y + x.z*p0.z + x.w*p0.w;
            x = row0[lane+32];   acc0 += x.x*p1.x + x.y*p1.y + x.z*p1.z + x.w*p1.w;
            x = row0[lane+64];   acc0 += x.x*p2.x + x.y*p2.y + x.z*p2.z + x.w*p2.w;
            x = row0[lane+96];   acc0 += x.x*p3.x + x.y*p3.y + x.z*p3.z + x.w*p3.w;
            x = row1[lane];      acc1  = x.x*p0.x + x.y*p0.y + x.z*p0.z + x.w*p0.w;
            x = row1[lane+32];   acc1 += x.x*p1.x + x.y*p1.y + x.z*p1.z + x.w*p1.w;
            x = row1[lane+64];   acc1 += x.x*p2.x + x.y*p2.y + x.z*p2.z + x.w*p2.w;
            x = row1[lane+96];   acc1 += x.x*p3.x + x.y*p3.y + x.z*p3.z + x.w*p3.w;
            x = row2[lane];      acc2  = x.x*p0.x + x.y*p0.y + x.z*p0.z + x.w*p0.w;
            x = row2[lane+32];   acc2 += x.x*p1.x + x.y*p1.y + x.z*p1.z + x.w*p1.w;
            x = row2[lane+64];   acc2 += x.x*p2.x + x.y*p2.y + x.z*p2.z + x.w*p2.w;
            x = row2[lane+96];   acc2 += x.x*p3.x + x.y*p3.y + x.z*p3.z + x.w*p3.w;
            x = row3[lane];      acc3  = x.x*p0.x + x.y*p0.y + x.z*p0.z + x.w*p0.w;
            x = row3[lane+32];   acc3 += x.x*p1.x + x.y*p1.y + x.z*p1.z + x.w*p1.w;
            x = row3[lane+64];   acc3 += x.x*p2.x + x.y*p2.y + x.z*p2.z + x.w*p2.w;
            x = row3[lane+96];   acc3 += x.x*p3.x + x.y*p3.y + x.z*p3.z + x.w*p3.w;
        }
        #pragma unroll
        for (int off = 16; off; off >>= 1) {
            acc0 += __shfl_xor_sync(0xFFFFFFFFu, acc0, off);
            acc1 += __shfl_xor_sync(0xFFFFFFFFu, acc1, off);
            acc2 += __shfl_xor_sync(0xFFFFFFFFu, acc2, off);
            acc3 += __shfl_xor_sync(0xFFFFFFFFu, acc3, off);
        }
        if (lane < 4) {
            const float sel = (lane == 0) ? acc0 : (lane == 1) ? acc1 : (lane == 2) ? acc2 : acc3;
            s_part[q][4*a + lane] = sel;
        }
        __syncthreads();

        // warp0: finalize 16 states, publish row, vote nz, prefetch next emission
        unsigned cta_nz = 0u;
        if (wid == 0) {
            float v = 0.f;
            if (lane < SPS) {
                v = (s_part[0][lane] + s_part[1][lane] + s_part[2][lane] + s_part[3][lane]) * em;
                __stcg(out + (size_t)t * NSTATES + sbase + lane, v);
            }
            __threadfence();                       // order row store before barrier arrival
            cta_nz = __ballot_sync(0xFFFFFFFFu, v != 0.f) ? 1u : 0u;
            if (lane < SPS)
                em = __ldcg(B + (size_t)my_s * NSYM + o_next);
        }
        __syncthreads();                           // all warps done with s_part
        if (tid == 0) s_nz = grid_bar_nz(cta_nz);
        __syncthreads();
    }

    // ---------------- Tail: zero-fill rows t..TLEN-1 ----------------
    if (t < TLEN) {
        float4* out4 = (float4*)out;
        const size_t begin  = (size_t)t * (NSTATES / 4);
        const size_t total4 = (size_t)TLEN * (NSTATES / 4);
        const float4 z = make_float4(0.f, 0.f, 0.f, 0.f);
        for (size_t i = begin + (size_t)b * NTHR + tid; i < total4;
             i += (size_t)NBLK * NTHR)
            out4[i] = z;
    }
}

extern "C" void kernel_launch(void* const* d_in, const int* in_sizes, int n_in,
                              void* d_out, int out_size)
{
    (void)in_sizes; (void)n_in; (void)out_size;
    const int*   obs = (const int*)d_in[0];
    const float* A   = (const float*)d_in[1];
    const float* B   = (const float*)d_in[2];
    const float* pi  = (const float*)d_in[3];
    float*       out = (float*)d_out;

    const int smem_bytes = SPS * NSTATES * (int)sizeof(float);  // 128 KB
    cudaFuncSetAttribute(hmm_forward_kernel,
                         cudaFuncAttributeMaxDynamicSharedMemorySize, smem_bytes);
    hmm_forward_kernel<<<NBLK, NTHR, smem_bytes>>>(obs, A, B, pi, out);
}

// round 10
// speedup vs baseline: 2.6733x; 1.3285x over previous
#include <cuda_runtime.h>
#include <cstdint>

#define NSTATES 2048
#define NSYM    512
#define TLEN    8192
#define NBLK    128
#define NTHR    512
#define SPS     16               // states per CTA
#define QRT     (NSTATES / 4)    // j-values per quarter
#define SCR_ROWS 64              // sentinel scratch rows (chain dies ~t=16; fallback if exceeded)

// Sentinel scratch for the alpha chain (rows 1..SCR_ROWS-1 reset to -1 each replay).
__device__ float g_alpha[SCR_ROWS * NSTATES];

// Central barrier (startup + fallback only). Graph-replay safe: gen monotone, cnt returns to 0.
__device__ volatile unsigned g_bar_gen;
__device__ unsigned          g_bar_cnt;
__device__ volatile unsigned g_nz_res;

__device__ __forceinline__ unsigned grid_bar_nz(unsigned cta_nz) {
    const unsigned g = g_bar_gen;
    const unsigned old = atomicAdd(&g_bar_cnt, 1u | (cta_nz << 16));
    if ((old & 0xFFFFu) == NBLK - 1) {
        const unsigned tot = (old >> 16) + cta_nz;
        g_nz_res = tot;
        *((volatile unsigned*)&g_bar_cnt) = 0u;
        __threadfence();
        g_bar_gen = g + 1;
        return tot;
    }
    while (g_bar_gen == g) { }
    return g_nz_res;
}

// Un-hoistable L2 load (the R5 lesson: never spin on a non-volatile load).
__device__ __forceinline__ float4 ldvol4(const float* p) {
    float4 v;
    asm volatile("ld.volatile.global.v4.f32 {%0,%1,%2,%3}, [%4];"
                 : "=f"(v.x), "=f"(v.y), "=f"(v.z), "=f"(v.w) : "l"(p));
    return v;
}
__device__ __forceinline__ unsigned bits4(const float4& v) {
    return __float_as_uint(v.x) | __float_as_uint(v.y) |
           __float_as_uint(v.z) | __float_as_uint(v.w);
}

__global__ __launch_bounds__(NTHR, 1)
void hmm_forward_kernel(const int* __restrict__ obs,
                        const float* __restrict__ A,
                        const float* __restrict__ B,
                        const float* __restrict__ pi,
                        float* __restrict__ out)
{
    extern __shared__ float s_At[];          // [SPS][NSTATES] = 128 KB
    __shared__ float s_part[4][SPS];
    __shared__ unsigned s_qnz[4];
    __shared__ unsigned s_nz;

    const int tid   = threadIdx.x;
    const int lane  = tid & 31;
    const int wid   = tid >> 5;
    const int b     = blockIdx.x;
    const int sbase = b * SPS;
    const int my_s  = sbase + (lane & 15);

    float em = 0.f;                          // B[my_s][obs[t]] for upcoming row t (warp0 lanes<16)
    float last_v = 0.f;                      // warp0: last produced value (for fallback vote)

    // ---------------- Row 0 (out + scratch) + em prefetch (warp 0) ----------------
    unsigned nz0 = 1u;
    if (wid == 0) {
        float v = 0.f;
        if (lane < SPS) {
            const int o0 = __ldcg(obs);
            v = __ldcg(pi + my_s) * __ldcg(B + (size_t)my_s * NSYM + o0);
            __stcg(out + my_s, v);
            __stcg(g_alpha + my_s, v);
        }
        last_v = v;
        __threadfence();
        nz0 = __ballot_sync(0xFFFFFFFFu, v != 0.f) ? 1u : 0u;
        if (lane < SPS) {
            const int o1 = __ldcg(obs + 1);
            em = __ldcg(B + (size_t)my_s * NSYM + o1);
        }
    }

    // ---------------- Sentinel reset: scratch rows 1..SCR_ROWS-1 ----------------
    {
        const int base = NSTATES;                        // skip row 0
        const int cnt  = (SCR_ROWS - 1) * NSTATES;       // 129024 floats
        for (int i = b * NTHR + tid; i < cnt; i += NBLK * NTHR)
            __stcg(g_alpha + base + i, -1.0f);
    }

    // ---------------- Load A columns [sbase,sbase+16), transpose into smem (MLP 8) ----------------
    {
        const int r  = tid >> 2;             // 0..127
        const int c0 = (tid & 3) << 2;       // 0,4,8,12
        const float* Ag = A + sbase + c0;
        #pragma unroll
        for (int p = 0; p < 16; p += 8) {
            float4 v[8];
            int jj[8];
            #pragma unroll
            for (int u = 0; u < 8; ++u) {
                jj[u] = (p + u) * 128 + r;
                v[u] = __ldcg((const float4*)(Ag + (size_t)jj[u] * NSTATES));
            }
            #pragma unroll
            for (int u = 0; u < 8; ++u) {
                s_At[(c0+0)*NSTATES + jj[u]] = v[u].x;
                s_At[(c0+1)*NSTATES + jj[u]] = v[u].y;
                s_At[(c0+2)*NSTATES + jj[u]] = v[u].z;
                s_At[(c0+3)*NSTATES + jj[u]] = v[u].w;
            }
        }
    }
    __syncthreads();
    if (tid == 0) s_nz = grid_bar_nz(nz0);   // sentinel reset + row 0 now globally visible
    __syncthreads();

    // ---------------- Main loop: sentinel-spin dataflow, register-tile GEMV ----------------
    const int a = wid >> 2;                  // local states 4a..4a+3
    const int q = wid & 3;                   // j quarter
    const float4* row0 = (const float4*)(s_At + (size_t)(4*a + 0) * NSTATES + q * QRT);
    const float4* row1 = (const float4*)(s_At + (size_t)(4*a + 1) * NSTATES + q * QRT);
    const float4* row2 = (const float4*)(s_At + (size_t)(4*a + 2) * NSTATES + q * QRT);
    const float4* row3 = (const float4*)(s_At + (size_t)(4*a + 3) * NSTATES + q * QRT);
    const bool poller = (wid < 4);           // warp w<4 polls quarter q==wid (its own quarter)

    bool zero_break = false;
    int t;
    for (t = 1; t < SCR_ROWS; ++t) {
        const float* al = g_alpha + (size_t)(t - 1) * NSTATES + q * QRT;
        float4 p0, p1, p2, p3;

        if (poller) {
            for (;;) {
                p0 = ldvol4(al + 4*lane);
                p1 = ldvol4(al + 4*(lane + 32));
                p2 = ldvol4(al + 4*(lane + 64));
                p3 = ldvol4(al + 4*(lane + 96));
                const unsigned sg = (bits4(p0)|bits4(p1)|bits4(p2)|bits4(p3)) & 0x80000000u;
                if (__all_sync(0xFFFFFFFFu, sg == 0u)) break;
            }
            const unsigned ob = bits4(p0)|bits4(p1)|bits4(p2)|bits4(p3);
            const bool qnz = __any_sync(0xFFFFFFFFu, ob != 0u);
            if (lane == 0) s_qnz[wid] = qnz ? 1u : 0u;
        }
        int o_next = 0;
        if (wid == 0 && lane < SPS)
            o_next = __ldcg(obs + ((t + 1 < TLEN) ? t + 1 : t));

        __syncthreads();                     // row t-1 valid everywhere; s_qnz ready
        if (!(s_qnz[0] | s_qnz[1] | s_qnz[2] | s_qnz[3])) { zero_break = true; break; }

        if (!poller) {
            const float4* alv = (const float4*)al;
            p0 = __ldcg(alv + lane);
            p1 = __ldcg(alv + lane + 32);
            p2 = __ldcg(alv + lane + 64);
            p3 = __ldcg(alv + lane + 96);
        }

        float acc0, acc1, acc2, acc3;
        {
            float4 x;
            x = row0[lane];      acc0  = x.x*p0.x + x.y*p0.y + x.z*p0.z + x.w*p0.w;
            x = row0[lane+32];   acc0 += x.x*p1.x + x.y*p1.y + x.z*p1.z + x.w*p1.w;
            x = row0[lane+64];   acc0 += x.x*p2.x + x.y*p2.y + x.z*p2.z + x.w*p2.w;
            x = row0[lane+96];   acc0 += x.x*p3.x + x.y*p3.y + x.z*p3.z + x.w*p3.w;
            x = row1[lane];      acc1  = x.x*p0.x + x.y*p0.y + x.z*p0.z + x.w*p0.w;
            x = row1[lane+32];   acc1 += x.x*p1.x + x.y*p1.y + x.z*p1.z + x.w*p1.w;
            x = row1[lane+64];   acc1 += x.x*p2.x + x.y*p2.y + x.z*p2.z + x.w*p2.w;
            x = row1[lane+96];   acc1 += x.x*p3.x + x.y*p3.y + x.z*p3.z + x.w*p3.w;
            x = row2[lane];      acc2  = x.x*p0.x + x.y*p0.y + x.z*p0.z + x.w*p0.w;
            x = row2[lane+32];   acc2 += x.x*p1.x + x.y*p1.y + x.z*p1.z + x.w*p1.w;
            x = row2[lane+64];   acc2 += x.x*p2.x + x.y*p2.y + x.z*p2.z + x.w*p2.w;
            x = row2[lane+96];   acc2 += x.x*p3.x + x.y*p3.y + x.z*p3.z + x.w*p3.w;
            x = row3[lane];      acc3  = x.x*p0.x + x.y*p0.y + x.z*p0.z + x.w*p0.w;
            x = row3[lane+32];   acc3 += x.x*p1.x + x.y*p1.y + x.z*p1.z + x.w*p1.w;
            x = row3[lane+64];   acc3 += x.x*p2.x + x.y*p2.y + x.z*p2.z + x.w*p2.w;
            x = row3[lane+96];   acc3 += x.x*p3.x + x.y*p3.y + x.z*p3.z + x.w*p3.w;
        }
        #pragma unroll
        for (int off = 16; off; off >>= 1) {
            acc0 += __shfl_xor_sync(0xFFFFFFFFu, acc0, off);
            acc1 += __shfl_xor_sync(0xFFFFFFFFu, acc1, off);
            acc2 += __shfl_xor_sync(0xFFFFFFFFu, acc2, off);
            acc3 += __shfl_xor_sync(0xFFFFFFFFu, acc3, off);
        }
        if (lane < 4) {
            const float sel = (lane == 0) ? acc0 : (lane == 1) ? acc1 : (lane == 2) ? acc2 : acc3;
            s_part[q][4*a + lane] = sel;
        }
        __syncthreads();                     // partials ready for warp0

        if (wid == 0) {
            float v = 0.f;
            if (lane < SPS) {
                v = (s_part[0][lane] + s_part[1][lane] + s_part[2][lane] + s_part[3][lane]) * em;
                __stcg(out + (size_t)t * NSTATES + sbase + lane, v);
                __stcg(g_alpha + (size_t)t * NSTATES + sbase + lane, v);  // un-sentinels row t
            }
            last_v = v;
            if (lane < SPS)
                em = __ldcg(B + (size_t)my_s * NSYM + o_next);
        }
        // no extra sync: fast warps block on next row's sentinel (written only after
        // warp0 passes this point); s_part/s_qnz writes for t+1 happen after syncthreads above.
    }

    // ---------------- Fallback (chain outlived scratch; never hit for this data) ----------------
    if (!zero_break && t == SCR_ROWS) {
        unsigned cta_nz = 0u;
        if (wid == 0) {
            __threadfence();
            cta_nz = __ballot_sync(0xFFFFFFFFu, last_v != 0.f) ? 1u : 0u;
        }
        __syncthreads();
        if (tid == 0) s_nz = grid_bar_nz(cta_nz);
        __syncthreads();

        for (; t < TLEN; ++t) {
            if (!s_nz) break;
            const float4* al = (const float4*)(out + (size_t)(t - 1) * NSTATES) + q * (QRT / 4);
            float4 p0 = __ldcg(al + lane);
            float4 p1 = __ldcg(al + lane + 32);
            float4 p2 = __ldcg(al + lane + 64);
            float4 p3 = __ldcg(al + lane + 96);
            int o_next = 0;
            if (wid == 0 && lane < SPS)
                o_next = __ldcg(obs + ((t + 1 < TLEN) ? t + 1 : t));

            float acc0, acc1, acc2, acc3;
            {
                float4 x;
                x = row0[lane];      acc0  = x.x*p0.x + x.y*p0.y + x.z*p0.z + x.w*p0.w;
                x = row0[lane+32];   acc0 += x.x*p1.x + x.y*p1.y + x.z*p1.z + x.w*p1.w;
                x = row0[lane+64];   acc0 += x.x*p2.x + x.y*p2.y + x.z*p2.z + x.w*p2.w;
                x = row0[lane+96];   acc0 += x.x*p3.x + x.y*p3.y + x.z*p3.z + x.w*p3.w;
                x = row1[lane];      acc1  = x.x*p0.x + x.y*p0.y + x.z*p0.z + x.w*p0.w;
                x = row1[lane+32];   acc1 += x.x*p1.x + x.y*p1.y + x.z*p1.z + x.w*p1.w;
                x = row1[lane+64];   acc1 += x.x*p2.x + x.y*p2.y + x.z*p2.z + x.w*p2.w;
                x = row1[lane+96];   acc1 += x.x*p3.x + x.y*p3.y + x.z*p3.z + x.w*p3.w;
                x = row2[lane];      acc2  = x.x*p0.x + x.y*p0.y + x.z*p0.z + x.w*p0.w;
                x = row2[lane+32];   acc2 += x.x*p1.x + x.y*p1.y + x.z*p1.z + x.w*p1.w;
                x = row2[lane+64];   acc2 += x.x*p2.x + x.y*p2.y + x.z*p2.z + x.w*p2.w;
                x = row2[lane+96];   acc2 += x.x*p3.x + x.y*p3.y + x.z*p3.z + x.w*p3.w;
                x = row3[lane];      acc3  = x.x*p0.x + x.y*p0.y + x.z*p0.z + x.w*p0.w;
                x = row3[lane+32];   acc3 += x.x*p1.x + x.y*p1.y + x.z*p1.z + x.w*p1.w;
                x = row3[lane+64];   acc3 += x.x*p2.x + x.y*p2.y + x.z*p2.z + x.w*p2.w;
                x = row3[lane+96];   acc3 += x.x*p3.x + x.y*p3.y + x.z*p3.z + x.w*p3.w;
            }
            #pragma unroll
            for (int off = 16; off; off >>= 1) {
                acc0 += __shfl_xor_sync(0xFFFFFFFFu, acc0, off);
                acc1 += __shfl_xor_sync(0xFFFFFFFFu, acc1, off);
                acc2 += __shfl_xor_sync(0xFFFFFFFFu, acc2, off);
                acc3 += __shfl_xor_sync(0xFFFFFFFFu, acc3, off);
            }
            if (lane < 4) {
                const float sel = (lane == 0) ? acc0 : (lane == 1) ? acc1 : (lane == 2) ? acc2 : acc3;
                s_part[q][4*a + lane] = sel;
            }
            __syncthreads();

            unsigned cnz = 0u;
            if (wid == 0) {
                float v = 0.f;
                if (lane < SPS) {
                    v = (s_part[0][lane] + s_part[1][lane] + s_part[2][lane] + s_part[3][lane]) * em;
                    __stcg(out + (size_t)t * NSTATES + sbase + lane, v);
                }
                __threadfence();
                cnz = __ballot_sync(0xFFFFFFFFu, v != 0.f) ? 1u : 0u;
                if (lane < SPS)
                    em = __ldcg(B + (size_t)my_s * NSYM + o_next);
            }
            __syncthreads();
            if (tid == 0) s_nz = grid_bar_nz(cnz);
            __syncthreads();
        }
    }

    // ---------------- Tail: zero-fill rows t..TLEN-1 ----------------
    if (t < TLEN) {
        float4* out4 = (float4*)out;
        const size_t begin  = (size_t)t * (NSTATES / 4);
        const size_t total4 = (size_t)TLEN * (NSTATES / 4);
        const float4 z = make_float4(0.f, 0.f, 0.f, 0.f);
        for (size_t i = begin + (size_t)b * NTHR + tid; i < total4;
             i += (size_t)NBLK * NTHR)
            out4[i] = z;
    }
}

extern "C" void kernel_launch(void* const* d_in, const int* in_sizes, int n_in,
                              void* d_out, int out_size)
{
    (void)in_sizes; (void)n_in; (void)out_size;
    const int*   obs = (const int*)d_in[0];
    const float* A   = (const float*)d_in[1];
    const float* B   = (const float*)d_in[2];
    const float* pi  = (const float*)d_in[3];
    float*       out = (float*)d_out;

    const int smem_bytes = SPS * NSTATES * (int)sizeof(float);  // 128 KB
    cudaFuncSetAttribute(hmm_forward_kernel,
                         cudaFuncAttributeMaxDynamicSharedMemorySize, smem_bytes);
    hmm_forward_kernel<<<NBLK, NTHR, smem_bytes>>>(obs, A, B, pi, out);
}